// round 2
// baseline (speedup 1.0000x reference)
#include <cuda_runtime.h>
#include <math.h>

// Problem-size constants (fixed by the reference).
#define MAXN 100000
#define FDIM 64          // F == H*D == 64
#define NH   8
#define HD   8
#define CLIPV 5.0f
#define INV_SQRT_D 0.35355339059327373f  // 1/sqrt(8)

// ---------------- scratch (device globals; no allocations allowed) ---------
__device__ float g_Q [MAXN * FDIM];
__device__ float g_K [MAXN * FDIM];
__device__ float g_V [MAXN * FDIM];
__device__ float g_wV[MAXN * FDIM];
__device__ float g_z [MAXN * NH];

// ---------------- f32x2 packed helpers (Blackwell) --------------------------
__device__ __forceinline__ unsigned long long dup_f32(float x) {
    unsigned long long r;
    asm("mov.b64 %0, {%1, %1};" : "=l"(r) : "f"(x));
    return r;
}
#define FMA_F32X2(d, a, b) \
    asm("fma.rn.f32x2 %0, %1, %2, %3;" : "=l"(d) : "l"(a), "l"(b), "l"(d))

__device__ __forceinline__ void unpack_f32x2(unsigned long long v, float& lo, float& hi) {
    asm("mov.b64 {%0, %1}, %2;" : "=f"(lo), "=f"(hi) : "l"(v));
}

__device__ __forceinline__ void red_add_v2(float* p, float x, float y) {
    asm volatile("red.global.add.v2.f32 [%0], {%1, %2};"
                 :: "l"(p), "f"(x), "f"(y) : "memory");
}

// ---------------- zero accumulators ----------------------------------------
__global__ void zero_kernel(float* wV, float* z, int N)
{
    int total = N * FDIM + N * NH;
    for (int i = blockIdx.x * blockDim.x + threadIdx.x; i < total;
         i += gridDim.x * blockDim.x) {
        if (i < N * FDIM) wV[i] = 0.0f;
        else              z[i - N * FDIM] = 0.0f;
    }
}

// ---------------- shared GEMM micro-kernel ----------------------------------
// XsT: [64][68], XsT[k][m] = X[m0+m][k]    (transposed tile)
// WT : [64][68], WT[k][n]  = W[n][k]
// Computes acc2[i][p] = packed pair (Y[ty*4+i][tx*4+2p], Y[ty*4+i][tx*4+2p+1])
__device__ __forceinline__ void gemm_tile_f32x2(const float* __restrict__ XsT,
                                                const float* __restrict__ WT,
                                                unsigned long long acc2[4][2],
                                                int tx, int ty)
{
    #pragma unroll
    for (int i = 0; i < 4; i++) { acc2[i][0] = 0ULL; acc2[i][1] = 0ULL; }
    #pragma unroll 4
    for (int k = 0; k < 64; k++) {
        float4 a4 = *(const float4*)(XsT + k * 68 + ty * 4);
        ulonglong2 wp = *(const ulonglong2*)(WT + k * 68 + tx * 4);
        unsigned long long a0 = dup_f32(a4.x);
        unsigned long long a1 = dup_f32(a4.y);
        unsigned long long a2 = dup_f32(a4.z);
        unsigned long long a3 = dup_f32(a4.w);
        FMA_F32X2(acc2[0][0], a0, wp.x); FMA_F32X2(acc2[0][1], a0, wp.y);
        FMA_F32X2(acc2[1][0], a1, wp.x); FMA_F32X2(acc2[1][1], a1, wp.y);
        FMA_F32X2(acc2[2][0], a2, wp.x); FMA_F32X2(acc2[2][1], a2, wp.y);
        FMA_F32X2(acc2[3][0], a3, wp.x); FMA_F32X2(acc2[3][1], a3, wp.y);
    }
}

// Stage X tile transposed: XsT[k][m] = X[m0+m][k]  (zero-pad rows >= M)
__device__ __forceinline__ void stage_xt(const float* __restrict__ X, int m0, int M,
                                         float* __restrict__ XsT, int tid)
{
    #pragma unroll
    for (int i = 0; i < 16; i++) {
        int idx = tid + 256 * i;
        int mm  = idx >> 6;
        int kk  = idx & 63;
        int m   = m0 + mm;
        XsT[kk * 68 + mm] = (m < M) ? X[(size_t)m * 64 + kk] : 0.0f;
    }
}

// Stage W transposed: WT[k][n] = W[n][k]
__device__ __forceinline__ void stage_wt(const float* __restrict__ W,
                                         float* __restrict__ WT, int tid)
{
    #pragma unroll
    for (int i = 0; i < 16; i++) {
        int idx = tid + 256 * i;
        int n = idx & 63;
        int k = idx >> 6;
        WT[k * 68 + n] = W[n * 64 + k];
    }
}

// ---------------- fused Q/K/V projection ------------------------------------
// One block = 64 nodes; X tile staged once, loop over 3 weight matrices.
__global__ void __launch_bounds__(256)
qkv_kernel(const float* __restrict__ X,
           const float* __restrict__ Wq, const float* __restrict__ bq,
           const float* __restrict__ Wk, const float* __restrict__ bk,
           const float* __restrict__ Wv, const float* __restrict__ bv,
           float* __restrict__ Q, float* __restrict__ K, float* __restrict__ V,
           int M)
{
    __shared__ float XsT[64 * 68];
    __shared__ float WT [64 * 68];

    const int tid = threadIdx.x;
    const int tx  = tid & 15;
    const int ty  = tid >> 4;
    const int m0  = blockIdx.x * 64;

    stage_xt(X, m0, M, XsT, tid);

    const float* Ws[3] = { Wq, Wk, Wv };
    const float* bs[3] = { bq, bk, bv };
    float*       Ys[3] = { Q,  K,  V  };

    #pragma unroll 1
    for (int mat = 0; mat < 3; mat++) {
        __syncthreads();               // protect WT from previous pass readers
        stage_wt(Ws[mat], WT, tid);
        __syncthreads();

        unsigned long long acc2[4][2];
        gemm_tile_f32x2(XsT, WT, acc2, tx, ty);

        float4 b4 = *(const float4*)&bs[mat][tx * 4];
        float* Y = Ys[mat];
        #pragma unroll
        for (int i = 0; i < 4; i++) {
            int m = m0 + ty * 4 + i;
            if (m < M) {
                float4 o;
                unpack_f32x2(acc2[i][0], o.x, o.y);
                unpack_f32x2(acc2[i][1], o.z, o.w);
                o.x += b4.x; o.y += b4.y; o.z += b4.z; o.w += b4.w;
                *(float4*)&Y[(size_t)m * 64 + tx * 4] = o;
            }
        }
    }
}

// ---------------- fused edge projection + attention -------------------------
// One block = 64 edges. Phase 1: GEMM proj_e tile (into regs). Phase 2: park
// the tile in smem (aliasing the dead X/W staging buffers). Phase 3: per-edge
// attention math + scatter (warp per edge, 8 edges per warp).
__global__ void __launch_bounds__(256)
edge_kernel(const float* __restrict__ EF, const float* __restrict__ We,
            const float* __restrict__ be,
            const float* __restrict__ Q, const float* __restrict__ K,
            const float* __restrict__ V,
            const int* __restrict__ src, const int* __restrict__ dst,
            float* __restrict__ e_out, float* __restrict__ wV,
            float* __restrict__ z, int E)
{
    __shared__ float buf[2 * 64 * 68];    // phase 1/2: XsT+WT; phase 3: PEs
    float* XsT = buf;
    float* WT  = buf + 64 * 68;
    float* PEs = buf;                     // [64][68], aliases XsT/WT

    const int tid  = threadIdx.x;
    const int tx   = tid & 15;
    const int ty   = tid >> 4;
    const int warp = tid >> 5;
    const int lane = tid & 31;
    const int e0   = blockIdx.x * 64;

    stage_xt(EF, e0, E, XsT, tid);
    stage_wt(We, WT, tid);
    __syncthreads();

    unsigned long long acc2[4][2];
    gemm_tile_f32x2(XsT, WT, acc2, tx, ty);

    float4 b4 = *(const float4*)&be[tx * 4];
    __syncthreads();                      // everyone done reading XsT/WT

    #pragma unroll
    for (int i = 0; i < 4; i++) {
        float4 o;
        unpack_f32x2(acc2[i][0], o.x, o.y);
        unpack_f32x2(acc2[i][1], o.z, o.w);
        o.x += b4.x; o.y += b4.y; o.z += b4.z; o.w += b4.w;
        *(float4*)&PEs[(ty * 4 + i) * 68 + tx * 4] = o;
    }
    __syncthreads();

    // ---- attention: warp per edge, lane j owns dims (2j, 2j+1) ------------
    const int c = lane * 2;
    #pragma unroll 1
    for (int i = 0; i < 8; i++) {
        int e_loc = warp * 8 + i;
        int e = e0 + e_loc;
        if (e >= E) break;
        int s = __ldg(&src[e]);
        int d = __ldg(&dst[e]);

        float2 k2 = *(const float2*)&K[(size_t)s * 64 + c];
        float2 q2 = *(const float2*)&Q[(size_t)d * 64 + c];
        float  p  = k2.x * q2.x + k2.y * q2.y;
        p += __shfl_xor_sync(0xFFFFFFFFu, p, 1);
        p += __shfl_xor_sync(0xFFFFFFFFu, p, 2);   // dot over the head's 8 dims

        float sc = fminf(fmaxf(p * INV_SQRT_D, -CLIPV), CLIPV);

        float2 pe = *(const float2*)&PEs[e_loc * 68 + c];
        float2 sc2 = make_float2(sc * pe.x, sc * pe.y);
        *(float2*)&e_out[(size_t)e * 64 + c] = sc2;

        float t = sc2.x + sc2.y;
        t += __shfl_xor_sync(0xFFFFFFFFu, t, 1);
        t += __shfl_xor_sync(0xFFFFFFFFu, t, 2);
        float w = __expf(fminf(fmaxf(t, -CLIPV), CLIPV));

        float2 v2 = *(const float2*)&V[(size_t)s * 64 + c];
        red_add_v2(&wV[(size_t)d * 64 + c], v2.x * w, v2.y * w);
        if ((lane & 3) == 0)
            atomicAdd(&z[(size_t)d * NH + (lane >> 2)], w);
    }
}

// ---------------- finalize: h_out = wV / (z + 1e-6) ------------------------
__global__ void finalize_kernel(const float* __restrict__ wV,
                                const float* __restrict__ z,
                                float* __restrict__ h_out, int N)
{
    int total = N * FDIM;
    for (int i = blockIdx.x * blockDim.x + threadIdx.x; i < total;
         i += gridDim.x * blockDim.x) {
        int node = i >> 6;
        int head = (i & 63) >> 3;
        h_out[i] = wV[i] / (z[node * NH + head] + 1e-6f);
    }
}

// ---------------- launch ----------------------------------------------------
extern "C" void kernel_launch(void* const* d_in, const int* in_sizes, int n_in,
                              void* d_out, int out_size)
{
    const float* node_feats = (const float*)d_in[0];
    const float* edge_feats = (const float*)d_in[1];
    const int*   src        = (const int*)  d_in[2];
    const int*   dst        = (const int*)  d_in[3];
    const float* Wq = (const float*)d_in[4];  const float* bq = (const float*)d_in[5];
    const float* Wk = (const float*)d_in[6];  const float* bk = (const float*)d_in[7];
    const float* Wv = (const float*)d_in[8];  const float* bv = (const float*)d_in[9];
    const float* We = (const float*)d_in[10]; const float* be = (const float*)d_in[11];

    const int N = in_sizes[0] / FDIM;
    const int E = in_sizes[2];

    float *Qp, *Kp, *Vp, *wVp, *zp;
    cudaGetSymbolAddress((void**)&Qp,  g_Q);
    cudaGetSymbolAddress((void**)&Kp,  g_K);
    cudaGetSymbolAddress((void**)&Vp,  g_V);
    cudaGetSymbolAddress((void**)&wVp, g_wV);
    cudaGetSymbolAddress((void**)&zp,  g_z);

    float* out   = (float*)d_out;
    float* h_out = out;                       // [N, H, D] first
    float* e_out = out + (size_t)N * FDIM;    // [E, H, D] second

    // 1. zero accumulators
    {
        int total  = N * FDIM + N * NH;
        zero_kernel<<<(total + 255) / 256, 256>>>(wVp, zp, N);
    }
    // 2. fused Q/K/V projection
    {
        int blocks = (N + 63) / 64;
        qkv_kernel<<<blocks, 256>>>(node_feats, Wq, bq, Wk, bk, Wv, bv,
                                    Qp, Kp, Vp, N);
    }
    // 3. fused edge projection + attention + scatter
    {
        int blocks = (E + 63) / 64;
        edge_kernel<<<blocks, 256>>>(edge_feats, We, be, Qp, Kp, Vp,
                                     src, dst, e_out, wVp, zp, E);
    }
    // 4. finalize h_out
    {
        int total = N * FDIM;
        finalize_kernel<<<(total + 255) / 256, 256>>>(wVp, zp, h_out, N);
    }
}

// round 3
// speedup vs baseline: 1.0093x; 1.0093x over previous
#include <cuda_runtime.h>
#include <math.h>

// Problem-size constants (fixed by the reference).
#define MAXN 100000
#define FDIM 64          // F == H*D == 64
#define NH   8
#define HD   8
#define CLIPV 5.0f
#define INV_SQRT_D 0.35355339059327373f  // 1/sqrt(8)

// ---------------- scratch (device globals; no allocations allowed) ---------
__device__ float g_Q [MAXN * FDIM];
__device__ float g_K [MAXN * FDIM];
__device__ float g_V [MAXN * FDIM];
__device__ float g_wV[MAXN * FDIM];
__device__ float g_z [MAXN * NH];

// ---------------- f32x2 packed helpers (Blackwell) --------------------------
__device__ __forceinline__ unsigned long long dup_f32(float x) {
    unsigned long long r;
    asm("mov.b64 %0, {%1, %1};" : "=l"(r) : "f"(x));
    return r;
}
#define FMA_F32X2(d, a, b) \
    asm("fma.rn.f32x2 %0, %1, %2, %3;" : "=l"(d) : "l"(a), "l"(b), "l"(d))

__device__ __forceinline__ void unpack_f32x2(unsigned long long v, float& lo, float& hi) {
    asm("mov.b64 {%0, %1}, %2;" : "=f"(lo), "=f"(hi) : "l"(v));
}

__device__ __forceinline__ void red_add_v2(float* p, float x, float y) {
    asm volatile("red.global.add.v2.f32 [%0], {%1, %2};"
                 :: "l"(p), "f"(x), "f"(y) : "memory");
}

// ---------------- zero accumulators ----------------------------------------
__global__ void zero_kernel(float* wV, float* z, int N)
{
    int total = N * FDIM + N * NH;
    for (int i = blockIdx.x * blockDim.x + threadIdx.x; i < total;
         i += gridDim.x * blockDim.x) {
        if (i < N * FDIM) wV[i] = 0.0f;
        else              z[i - N * FDIM] = 0.0f;
    }
}

// ---------------- shared GEMM micro-kernel ----------------------------------
// XsT: [64][68], XsT[k][m] = X[m0+m][k]    (transposed tile)
// WT : [64][68], WT[k][n]  = W[n][k]
// Computes acc2[i][p] = packed pair (Y[ty*4+i][tx*4+2p], Y[ty*4+i][tx*4+2p+1])
__device__ __forceinline__ void gemm_tile_f32x2(const float* __restrict__ XsT,
                                                const float* __restrict__ WT,
                                                unsigned long long acc2[4][2],
                                                int tx, int ty)
{
    #pragma unroll
    for (int i = 0; i < 4; i++) { acc2[i][0] = 0ULL; acc2[i][1] = 0ULL; }
    #pragma unroll 4
    for (int k = 0; k < 64; k++) {
        float4 a4 = *(const float4*)(XsT + k * 68 + ty * 4);
        ulonglong2 wp = *(const ulonglong2*)(WT + k * 68 + tx * 4);
        unsigned long long a0 = dup_f32(a4.x);
        unsigned long long a1 = dup_f32(a4.y);
        unsigned long long a2 = dup_f32(a4.z);
        unsigned long long a3 = dup_f32(a4.w);
        FMA_F32X2(acc2[0][0], a0, wp.x); FMA_F32X2(acc2[0][1], a0, wp.y);
        FMA_F32X2(acc2[1][0], a1, wp.x); FMA_F32X2(acc2[1][1], a1, wp.y);
        FMA_F32X2(acc2[2][0], a2, wp.x); FMA_F32X2(acc2[2][1], a2, wp.y);
        FMA_F32X2(acc2[3][0], a3, wp.x); FMA_F32X2(acc2[3][1], a3, wp.y);
    }
}

// Stage X tile transposed: XsT[k][m] = X[m0+m][k]  (zero-pad rows >= M)
__device__ __forceinline__ void stage_xt(const float* __restrict__ X, int m0, int M,
                                         float* __restrict__ XsT, int tid)
{
    #pragma unroll
    for (int i = 0; i < 16; i++) {
        int idx = tid + 256 * i;
        int mm  = idx >> 6;
        int kk  = idx & 63;
        int m   = m0 + mm;
        XsT[kk * 68 + mm] = (m < M) ? X[(size_t)m * 64 + kk] : 0.0f;
    }
}

// Stage W transposed: WT[k][n] = W[n][k]
__device__ __forceinline__ void stage_wt(const float* __restrict__ W,
                                         float* __restrict__ WT, int tid)
{
    #pragma unroll
    for (int i = 0; i < 16; i++) {
        int idx = tid + 256 * i;
        int n = idx & 63;
        int k = idx >> 6;
        WT[k * 68 + n] = W[n * 64 + k];
    }
}

// ---------------- fused Q/K/V projection ------------------------------------
// One block = 64 nodes; X tile staged once, loop over 3 weight matrices.
__global__ void __launch_bounds__(256)
qkv_kernel(const float* __restrict__ X,
           const float* __restrict__ Wq, const float* __restrict__ bq,
           const float* __restrict__ Wk, const float* __restrict__ bk,
           const float* __restrict__ Wv, const float* __restrict__ bv,
           float* __restrict__ Q, float* __restrict__ K, float* __restrict__ V,
           int M)
{
    __shared__ float XsT[64 * 68];
    __shared__ float WT [64 * 68];

    const int tid = threadIdx.x;
    const int tx  = tid & 15;
    const int ty  = tid >> 4;
    const int m0  = blockIdx.x * 64;

    stage_xt(X, m0, M, XsT, tid);

    const float* Ws[3] = { Wq, Wk, Wv };
    const float* bs[3] = { bq, bk, bv };
    float*       Ys[3] = { Q,  K,  V  };

    #pragma unroll 1
    for (int mat = 0; mat < 3; mat++) {
        __syncthreads();               // protect WT from previous pass readers
        stage_wt(Ws[mat], WT, tid);
        __syncthreads();

        unsigned long long acc2[4][2];
        gemm_tile_f32x2(XsT, WT, acc2, tx, ty);

        float4 b4 = *(const float4*)&bs[mat][tx * 4];
        float* Y = Ys[mat];
        #pragma unroll
        for (int i = 0; i < 4; i++) {
            int m = m0 + ty * 4 + i;
            if (m < M) {
                float4 o;
                unpack_f32x2(acc2[i][0], o.x, o.y);
                unpack_f32x2(acc2[i][1], o.z, o.w);
                o.x += b4.x; o.y += b4.y; o.z += b4.z; o.w += b4.w;
                *(float4*)&Y[(size_t)m * 64 + tx * 4] = o;
            }
        }
    }
}

// ---------------- fused edge projection + attention -------------------------
// One block = 64 edges. Phase 1: GEMM proj_e tile (into regs). Phase 2: park
// the tile in smem (aliasing the dead X/W staging buffers). Phase 3: per-edge
// attention math + scatter, software-pipelined: ALL gathers for this warp's 8
// edges are issued before any compute/atomic (MLP ~24 instead of ~3).
__global__ void __launch_bounds__(256)
edge_kernel(const float* __restrict__ EF, const float* __restrict__ We,
            const float* __restrict__ be,
            const float* __restrict__ Q, const float* __restrict__ K,
            const float* __restrict__ V,
            const int* __restrict__ src, const int* __restrict__ dst,
            float* __restrict__ e_out, float* __restrict__ wV,
            float* __restrict__ z, int E)
{
    __shared__ float buf[2 * 64 * 68];    // phase 1/2: XsT+WT; phase 3: PEs
    float* XsT = buf;
    float* WT  = buf + 64 * 68;
    float* PEs = buf;                     // [64][68], aliases XsT/WT

    const int tid  = threadIdx.x;
    const int tx   = tid & 15;
    const int ty   = tid >> 4;
    const int warp = tid >> 5;
    const int lane = tid & 31;
    const int e0   = blockIdx.x * 64;

    stage_xt(EF, e0, E, XsT, tid);
    stage_wt(We, WT, tid);
    __syncthreads();

    unsigned long long acc2[4][2];
    gemm_tile_f32x2(XsT, WT, acc2, tx, ty);

    float4 b4 = *(const float4*)&be[tx * 4];
    __syncthreads();                      // everyone done reading XsT/WT

    #pragma unroll
    for (int i = 0; i < 4; i++) {
        float4 o;
        unpack_f32x2(acc2[i][0], o.x, o.y);
        unpack_f32x2(acc2[i][1], o.z, o.w);
        o.x += b4.x; o.y += b4.y; o.z += b4.z; o.w += b4.w;
        *(float4*)&PEs[(ty * 4 + i) * 68 + tx * 4] = o;
    }
    __syncthreads();

    // ---- attention: warp per edge-group of 8; lane j owns dims (2j,2j+1) --
    const int c      = lane * 2;
    const int e_base = e0 + warp * 8;
    const int nE     = min(8, E - e_base);   // E is a multiple of 64 in practice

    // (a) uniform loads of src/dst for all 8 edges (broadcast, 1-2 sectors)
    int s[8], d[8];
    #pragma unroll
    for (int i = 0; i < 8; i++) {
        bool ok = (i < nE);
        s[i] = ok ? __ldg(&src[e_base + i]) : 0;
        d[i] = ok ? __ldg(&dst[e_base + i]) : 0;
    }

    // (b) issue ALL row gathers before any compute — maximize MLP
    float2 k2[8], q2[8], v2[8];
    #pragma unroll
    for (int i = 0; i < 8; i++) {
        k2[i] = *(const float2*)&K[(size_t)s[i] * 64 + c];
        q2[i] = *(const float2*)&Q[(size_t)d[i] * 64 + c];
    }
    #pragma unroll
    for (int i = 0; i < 8; i++) {
        v2[i] = *(const float2*)&V[(size_t)s[i] * 64 + c];
    }

    // (c) compute + store + scatter
    #pragma unroll
    for (int i = 0; i < 8; i++) {
        if (i >= nE) break;
        float p = k2[i].x * q2[i].x + k2[i].y * q2[i].y;
        p += __shfl_xor_sync(0xFFFFFFFFu, p, 1);
        p += __shfl_xor_sync(0xFFFFFFFFu, p, 2);   // dot over the head's 8 dims

        float sc = fminf(fmaxf(p * INV_SQRT_D, -CLIPV), CLIPV);

        float2 pe  = *(const float2*)&PEs[(warp * 8 + i) * 68 + c];
        float2 sc2 = make_float2(sc * pe.x, sc * pe.y);
        *(float2*)&e_out[(size_t)(e_base + i) * 64 + c] = sc2;

        float t = sc2.x + sc2.y;
        t += __shfl_xor_sync(0xFFFFFFFFu, t, 1);
        t += __shfl_xor_sync(0xFFFFFFFFu, t, 2);
        float w = __expf(fminf(fmaxf(t, -CLIPV), CLIPV));

        red_add_v2(&wV[(size_t)d[i] * 64 + c], v2[i].x * w, v2[i].y * w);
        if ((lane & 3) == 0)
            atomicAdd(&z[(size_t)d[i] * NH + (lane >> 2)], w);
    }
}

// ---------------- finalize: h_out = wV / (z + 1e-6) ------------------------
__global__ void finalize_kernel(const float* __restrict__ wV,
                                const float* __restrict__ z,
                                float* __restrict__ h_out, int N)
{
    int total = N * FDIM;
    for (int i = blockIdx.x * blockDim.x + threadIdx.x; i < total;
         i += gridDim.x * blockDim.x) {
        int node = i >> 6;
        int head = (i & 63) >> 3;
        h_out[i] = wV[i] / (z[node * NH + head] + 1e-6f);
    }
}

// ---------------- launch ----------------------------------------------------
extern "C" void kernel_launch(void* const* d_in, const int* in_sizes, int n_in,
                              void* d_out, int out_size)
{
    const float* node_feats = (const float*)d_in[0];
    const float* edge_feats = (const float*)d_in[1];
    const int*   src        = (const int*)  d_in[2];
    const int*   dst        = (const int*)  d_in[3];
    const float* Wq = (const float*)d_in[4];  const float* bq = (const float*)d_in[5];
    const float* Wk = (const float*)d_in[6];  const float* bk = (const float*)d_in[7];
    const float* Wv = (const float*)d_in[8];  const float* bv = (const float*)d_in[9];
    const float* We = (const float*)d_in[10]; const float* be = (const float*)d_in[11];

    const int N = in_sizes[0] / FDIM;
    const int E = in_sizes[2];

    float *Qp, *Kp, *Vp, *wVp, *zp;
    cudaGetSymbolAddress((void**)&Qp,  g_Q);
    cudaGetSymbolAddress((void**)&Kp,  g_K);
    cudaGetSymbolAddress((void**)&Vp,  g_V);
    cudaGetSymbolAddress((void**)&wVp, g_wV);
    cudaGetSymbolAddress((void**)&zp,  g_z);

    float* out   = (float*)d_out;
    float* h_out = out;                       // [N, H, D] first
    float* e_out = out + (size_t)N * FDIM;    // [E, H, D] second

    // 1. zero accumulators
    {
        int total  = N * FDIM + N * NH;
        zero_kernel<<<(total + 255) / 256, 256>>>(wVp, zp, N);
    }
    // 2. fused Q/K/V projection
    {
        int blocks = (N + 63) / 64;
        qkv_kernel<<<blocks, 256>>>(node_feats, Wq, bq, Wk, bk, Wv, bv,
                                    Qp, Kp, Vp, N);
    }
    // 3. fused edge projection + attention + scatter
    {
        int blocks = (E + 63) / 64;
        edge_kernel<<<blocks, 256>>>(edge_feats, We, be, Qp, Kp, Vp,
                                     src, dst, e_out, wVp, zp, E);
    }
    // 4. finalize h_out
    {
        int total = N * FDIM;
        finalize_kernel<<<(total + 255) / 256, 256>>>(wVp, zp, h_out, N);
    }
}